// round 17
// baseline (speedup 1.0000x reference)
#include <cuda_runtime.h>
#include <math.h>

#define BB 128
#define TT 512
#define DD 300
#define HH 300
#define NG 1200      // 4*H
#define NGRP 16      // groups of 8 rows; one cluster per group
#define ROWSG 8

typedef unsigned long long u64;

// ---- packed f32x2 helpers (FFMA2: only reachable via PTX) ----
__device__ __forceinline__ u64 f2pack(float lo, float hi) {
    u64 d; asm("mov.b64 %0, {%1, %2};" : "=l"(d) : "f"(lo), "f"(hi)); return d;
}
__device__ __forceinline__ void f2unpack(u64 v, float& lo, float& hi) {
    asm("mov.b64 {%0, %1}, %2;" : "=f"(lo), "=f"(hi) : "l"(v));
}
__device__ __forceinline__ u64 f2fma(u64 a, u64 b, u64 c) {
    u64 d; asm("fma.rn.f32x2 %0, %1, %2, %3;" : "=l"(d) : "l"(a), "l"(b), "l"(c)); return d;
}

__device__ __forceinline__ unsigned smem_u32(const void* p) {
    unsigned a;
    asm("{ .reg .u64 t; cvta.to.shared.u64 t, %1; cvt.u32.u64 %0, t; }" : "=r"(a) : "l"(p));
    return a;
}

// ---- device scratch ----
__device__ float g_h[2][BB*HH];          // final-h handoff (parity len&1)
__device__ float g_xz[(size_t)BB*TT*NG]; // precomputed x@Wx + b_lstm
__device__ int   g_perm[BB];             // rows sorted by length descending

// ---------------------------------------------------------------------------
// init: zero h buffers; block 0 rank-sorts rows by length (desc) into g_perm.
// SORTED-CONTIGUOUS grouping (r13 winner): cluster g = ranks 8g..8g+7 ->
// only ONE cluster runs the full 512 steps, and clusters launch longest-first.
// ---------------------------------------------------------------------------
__global__ void init_kernel(const int* __restrict__ lengths) {
    int i = blockIdx.x * blockDim.x + threadIdx.x;
    if (i < BB*HH) { g_h[0][i] = 0.f; g_h[1][i] = 0.f; }
    __shared__ int sle[BB];
    if (blockIdx.x == 0) {
        if (threadIdx.x < BB) sle[threadIdx.x] = lengths[threadIdx.x];
        __syncthreads();
        if (threadIdx.x < BB) {
            int t  = threadIdx.x;
            int me = sle[t];
            int rank = 0;
            for (int j = 0; j < BB; j++)
                rank += (sle[j] > me) || (sle[j] == me && j < t);
            g_perm[rank] = t;
        }
    }
}

// ---------------------------------------------------------------------------
// precompute (double-buffered FFMA2 version, passing r16)
// ---------------------------------------------------------------------------
__global__ __launch_bounds__(256) void precompute_kernel(
    const int*   __restrict__ ids,
    const int*   __restrict__ lengths,
    const float* __restrict__ emb,
    const float* __restrict__ W,
    const float* __restrict__ bl)
{
    const int b  = blockIdx.z;
    const int t0 = blockIdx.y * 128;
    const int n0 = blockIdx.x * 64;
    if (lengths[b] <= t0) return;

    __shared__ float As[2][16][128];
    __shared__ float Bs[2][16][64];
    __shared__ int   toks[128];

    const int tid = threadIdx.x;
    if (tid < 128) toks[tid] = ids[b*TT + t0 + tid];

    const int tx = tid & 15;
    const int ty = tid >> 4;

    const int ar0  = tid >> 2,         akq0 = tid & 3;
    const int ar1  = (tid + 256) >> 2, akq1 = (tid + 256) & 3;
    const int bkk  = tid >> 4,         bq   = tid & 15;

    u64 acc2[4][4];
    #pragma unroll
    for (int i = 0; i < 4; i++)
        #pragma unroll
        for (int j = 0; j < 4; j++) acc2[i][j] = 0ull;

    __syncthreads();

    float4 ra0, ra1, rb;
    {
        int ka = akq0 * 4;
        ra0 = *(const float4*)(emb + (size_t)toks[ar0]*DD + ka);
        int kb = akq1 * 4;
        ra1 = *(const float4*)(emb + (size_t)toks[ar1]*DD + kb);
        int kw = bkk;
        int n  = n0 + bq * 4;
        rb = (n < NG) ? *(const float4*)(W + (size_t)kw*NG + n)
                      : make_float4(0.f, 0.f, 0.f, 0.f);
    }

    for (int ib = 0; ib < 19; ib++) {
        const int cb = ib & 1;
        As[cb][akq0*4+0][ar0] = ra0.x;
        As[cb][akq0*4+1][ar0] = ra0.y;
        As[cb][akq0*4+2][ar0] = ra0.z;
        As[cb][akq0*4+3][ar0] = ra0.w;
        As[cb][akq1*4+0][ar1] = ra1.x;
        As[cb][akq1*4+1][ar1] = ra1.y;
        As[cb][akq1*4+2][ar1] = ra1.z;
        As[cb][akq1*4+3][ar1] = ra1.w;
        *(float4*)&Bs[cb][bkk][bq*4] = rb;
        __syncthreads();

        if (ib < 18) {
            const int k0n = (ib + 1) * 16;
            int ka = k0n + akq0 * 4;
            ra0 = (ka < 300) ? *(const float4*)(emb + (size_t)toks[ar0]*DD + ka)
                             : make_float4(0.f, 0.f, 0.f, 0.f);
            int kb = k0n + akq1 * 4;
            ra1 = (kb < 300) ? *(const float4*)(emb + (size_t)toks[ar1]*DD + kb)
                             : make_float4(0.f, 0.f, 0.f, 0.f);
            int kw = k0n + bkk;
            int n  = n0 + bq * 4;
            rb = (kw < 300 && n < NG) ? *(const float4*)(W + (size_t)kw*NG + n)
                                      : make_float4(0.f, 0.f, 0.f, 0.f);
        }

        #pragma unroll
        for (int kk = 0; kk < 16; kk++) {
            float4 bv = *(const float4*)&Bs[cb][kk][tx*4];
            u64 b0 = f2pack(bv.x, bv.x);
            u64 b1 = f2pack(bv.y, bv.y);
            u64 b2 = f2pack(bv.z, bv.z);
            u64 b3 = f2pack(bv.w, bv.w);
            const u64* a2 = (const u64*)&As[cb][kk][ty*8];
            #pragma unroll
            for (int mp = 0; mp < 4; mp++) {
                u64 av = a2[mp];
                acc2[mp][0] = f2fma(av, b0, acc2[mp][0]);
                acc2[mp][1] = f2fma(av, b1, acc2[mp][1]);
                acc2[mp][2] = f2fma(av, b2, acc2[mp][2]);
                acc2[mp][3] = f2fma(av, b3, acc2[mp][3]);
            }
        }
        __syncthreads();
    }

    const int n = n0 + tx * 4;
    if (n < NG) {
        float4 blv = *(const float4*)(bl + n);
        #pragma unroll
        for (int mp = 0; mp < 4; mp++) {
            float x0,x1,y0,y1,z0,z1,q0,q1;
            f2unpack(acc2[mp][0], x0, x1);
            f2unpack(acc2[mp][1], y0, y1);
            f2unpack(acc2[mp][2], z0, z1);
            f2unpack(acc2[mp][3], q0, q1);
            int t = t0 + ty*8 + 2*mp;
            float4 o0 = make_float4(x0+blv.x, y0+blv.y, z0+blv.z, q0+blv.w);
            float4 o1 = make_float4(x1+blv.x, y1+blv.y, z1+blv.z, q1+blv.w);
            *(float4*)(g_xz + ((size_t)b*TT + t  )*NG + n) = o0;
            *(float4*)(g_xz + ((size_t)b*TT + t+1)*NG + n) = o1;
        }
    }
}

// ---------------------------------------------------------------------------
// persistent recurrence v10: templated cluster geometry.
// CLN CTAs per group-cluster, each owning UPCN units. Cluster dim is set at
// LAUNCH time (no __cluster_dims__): CL16 (non-portable) halves the per-SM
// matmul work on the critical cluster; CL8 instantiation == passing r13.
// h layout in hsm: unit u at chunk (u/KC2N) * KSTWN + (u%KC2N); matmul
// thread kc covers k in [kc*KC2N, (kc+1)*KC2N). Unit segments per CTA
// ([crank*UPCN, +UPCN)) never straddle a chunk (UPCN divides KC2N or
// KC2N = 2*UPCN), so h pairs push as one b64.
// ---------------------------------------------------------------------------
template<int UPCN, int KC2N, int KSTWN, int NSLN, int CLN>
__global__ __launch_bounds__(256, 1)
void lstm_persistent(
    const float* __restrict__ W,
    const int*   __restrict__ lengths)
{
    constexpr int WREG  = KC2N / 2;        // f32x2 regs per unit slot
    constexpr int HROWN = 8 * KSTWN;       // floats per staged h row
    constexpr int HBUFN = ROWSG * HROWN;   // floats per parity
    constexpr int ZROWN = 32 * NSLN;       // z floats per row (8 warps*NSLN*4)
    constexpr int PPCN  = UPCN / 2;        // unit pairs per CTA

    __shared__ __align__(16) float hsm[2][HBUFN];
    __shared__ __align__(16) float zsm[ROWSG*ZROWN];
    __shared__ int sli[ROWSG], spr[ROWSG];

    const int tid   = threadIdx.x;
    const int wid   = tid >> 5;
    const int lane  = tid & 31;
    const int kc    = lane >> 2;          // k-chunk 0..7
    const int gg    = lane & 3;           // gate
    const int gid   = blockIdx.x / CLN;
    const int crank = blockIdx.x % CLN;

    if (tid < ROWSG) {
        int pr = g_perm[gid*ROWSG + tid];
        spr[tid] = pr;
        sli[tid] = lengths[pr];
    }
    // zero both hsm parities (pad slots stay 0 forever)
    {
        float4 z4 = make_float4(0.f, 0.f, 0.f, 0.f);
        float4* p4 = (float4*)&hsm[0][0];
        for (int l = tid; l < 2*HBUFN/4; l += 256) p4[l] = z4;
    }

    // W -> registers: NSLN unit-slots x WREG f32x2 (this thread's k-chunk, gate)
    u64 w2[NSLN][WREG];
    #pragma unroll
    for (int jj = 0; jj < NSLN; jj++) {
        int  ul = wid*NSLN + jj;
        int  ug = crank*UPCN + ul;
        bool uv = (ul < UPCN) && (ug < HH);
        int  col = gg*HH + (uv ? ug : 0);
        #pragma unroll
        for (int i = 0; i < WREG; i++) {
            int k0 = kc*KC2N + 2*i;
            float lo = (uv && k0     < HH) ? W[(size_t)(HH + k0    )*NG + col] : 0.f;
            float hi = (uv && k0 + 1 < HH) ? W[(size_t)(HH + k0 + 1)*NG + col] : 0.f;
            w2[jj][i] = f2pack(lo, hi);
        }
    }
    __syncthreads();
    int slr[ROWSG];
    #pragma unroll
    for (int i = 0; i < ROWSG; i++) slr[i] = sli[i];
    const int maxlen = slr[0];

    // epilogue mapping: tid < 8*PPCN owns (row e_m, unit pair e_ug, e_ug+1)
    const bool e_has = (tid < ROWSG*PPCN);
    const int  e_m   = e_has ? tid/PPCN : 0;
    const int  e_jp  = e_has ? tid - e_m*PPCN : 0;
    const int  e_ul  = 2*e_jp;
    const int  e_ug  = crank*UPCN + e_ul;
    const bool e_val = e_has && (e_ug < HH);   // pairs fully valid/invalid (even)
    const int  e_b   = spr[e_m];
    const int  e_len = e_has ? slr[e_m] : 0;
    const int  e_chk = e_ug / KC2N;
    const int  e_pos = e_ug - e_chk*KC2N;
    const unsigned e_offb = (unsigned)((e_m*HROWN + e_chk*KSTWN + e_pos) * 4);
    const float* e_xbase = g_xz + (size_t)e_b*TT*NG + (e_val ? e_ug : 0);

    // mapa'd peer base addresses for hsm[0]
    unsigned rbase[CLN];
    {
        unsigned locb = smem_u32(&hsm[0][0]);
        #pragma unroll
        for (int r = 0; r < CLN; r++)
            asm("mapa.shared::cluster.u32 %0, %1, %2;"
                : "=r"(rbase[r]) : "r"(locb), "r"(r));
    }

    // all CTAs' hsm zero before any pushes can land
    asm volatile("barrier.cluster.arrive.aligned;" ::: "memory");
    asm volatile("barrier.cluster.wait.aligned;"   ::: "memory");

    float c0 = 0.f, c1 = 0.f;

    // prefetch xz for t = 0
    float pf[4][2];
    {
        const bool a0 = e_val && (0 < e_len);
        const float* xp = e_xbase;
        #pragma unroll
        for (int g = 0; g < 4; g++) {
            pf[g][0] = a0 ? __ldcg(xp + g*HH    ) : 0.f;
            pf[g][1] = a0 ? __ldcg(xp + g*HH + 1) : 0.f;
        }
    }

    for (int t = 0; t < maxlen; t++) {
        const int p = t & 1;
        const unsigned poff = (unsigned)(p ^ 1) * (unsigned)(HBUFN * 4);
        int nact = 0;
        #pragma unroll
        for (int i = 0; i < ROWSG; i++) nact += (slr[i] > t);
        const bool act = e_val && (t < e_len);

        // ---- matmul over active rows, 2 rows in flight ----
        const float* hp = &hsm[p][0];
        int m = 0;
        for (; m + 2 <= nact; m += 2) {
            const u64* hA = (const u64*)(hp + (m  )*HROWN + kc*KSTWN);
            const u64* hB = (const u64*)(hp + (m+1)*HROWN + kc*KSTWN);
            u64 accA[NSLN], accB[NSLN];
            #pragma unroll
            for (int j = 0; j < NSLN; j++) { accA[j] = 0ull; accB[j] = 0ull; }
            #pragma unroll
            for (int i = 0; i < WREG; i++) {
                u64 ha = hA[i];
                u64 hb = hB[i];
                #pragma unroll
                for (int j = 0; j < NSLN; j++) {
                    accA[j] = f2fma(w2[j][i], ha, accA[j]);
                    accB[j] = f2fma(w2[j][i], hb, accB[j]);
                }
            }
            float va[NSLN], vb[NSLN];
            #pragma unroll
            for (int j = 0; j < NSLN; j++) {
                float lo, hi;
                f2unpack(accA[j], lo, hi); va[j] = lo + hi;
                f2unpack(accB[j], lo, hi); vb[j] = lo + hi;
            }
            #pragma unroll
            for (int o = 4; o <= 16; o <<= 1) {
                #pragma unroll
                for (int j = 0; j < NSLN; j++) {
                    va[j] += __shfl_xor_sync(0xffffffffu, va[j], o);
                    vb[j] += __shfl_xor_sync(0xffffffffu, vb[j], o);
                }
            }
            if (lane < 4) {   // kc == 0; gg = lane
                #pragma unroll
                for (int j = 0; j < NSLN; j++) {
                    zsm[(m  )*ZROWN + (wid*NSLN + j)*4 + gg] = va[j];
                    zsm[(m+1)*ZROWN + (wid*NSLN + j)*4 + gg] = vb[j];
                }
            }
        }
        if (m < nact) {
            const u64* hA = (const u64*)(hp + m*HROWN + kc*KSTWN);
            u64 accA[NSLN];
            #pragma unroll
            for (int j = 0; j < NSLN; j++) accA[j] = 0ull;
            #pragma unroll
            for (int i = 0; i < WREG; i++) {
                u64 ha = hA[i];
                #pragma unroll
                for (int j = 0; j < NSLN; j++)
                    accA[j] = f2fma(w2[j][i], ha, accA[j]);
            }
            float va[NSLN];
            #pragma unroll
            for (int j = 0; j < NSLN; j++) {
                float lo, hi;
                f2unpack(accA[j], lo, hi); va[j] = lo + hi;
            }
            #pragma unroll
            for (int o = 4; o <= 16; o <<= 1) {
                #pragma unroll
                for (int j = 0; j < NSLN; j++)
                    va[j] += __shfl_xor_sync(0xffffffffu, va[j], o);
            }
            if (lane < 4) {
                #pragma unroll
                for (int j = 0; j < NSLN; j++)
                    zsm[m*ZROWN + (wid*NSLN + j)*4 + gg] = va[j];
            }
        }
        __syncthreads();

        // ---- epilogue: 2 units per thread; push h pair to all CLN CTAs ----
        if (act) {
            float4 za = *(const float4*)&zsm[e_m*ZROWN + e_ul*4];
            float4 zb = *(const float4*)&zsm[e_m*ZROWN + e_ul*4 + 4];
            // unit e_ug
            float zi = za.x + pf[0][0];
            float zj = za.y + pf[1][0];
            float zf = za.z + pf[2][0];
            float zo = za.w + pf[3][0];
            float si = 1.f / (1.f + __expf(-zi));
            float sf = 1.f / (1.f + __expf(-(zf + 1.f)));  // FORGET_BIAS=1
            float so = 1.f / (1.f + __expf(-zo));
            float tj = tanhf(zj);
            c0 = c0 * sf + si * tj;
            float h0 = tanhf(c0) * so;
            // unit e_ug+1
            zi = zb.x + pf[0][1];
            zj = zb.y + pf[1][1];
            zf = zb.z + pf[2][1];
            zo = zb.w + pf[3][1];
            si = 1.f / (1.f + __expf(-zi));
            sf = 1.f / (1.f + __expf(-(zf + 1.f)));
            so = 1.f / (1.f + __expf(-zo));
            tj = tanhf(zj);
            c1 = c1 * sf + si * tj;
            float h1 = tanhf(c1) * so;

            if (t == e_len - 1) {   // final state for this row: single handoff
                float* hwr = g_h[(t & 1) ^ 1];
                __stcg(&hwr[e_b*HH + e_ug],     h0);
                __stcg(&hwr[e_b*HH + e_ug + 1], h1);
            }

            u64 hv2 = f2pack(h0, h1);
            unsigned off = poff + e_offb;
            #pragma unroll
            for (int r = 0; r < CLN; r++)
                asm volatile("st.shared::cluster.b64 [%0], %1;"
                             :: "r"(rbase[r] + off), "l"(hv2) : "memory");
        }

        // ---- split barrier: arrive, prefetch next xz, then wait ----
        asm volatile("barrier.cluster.arrive.aligned;" ::: "memory");
        {
            const bool an = e_val && (t + 1 < e_len);
            const float* xp = e_xbase + (size_t)(t + 1)*NG;
            #pragma unroll
            for (int g = 0; g < 4; g++) {
                pf[g][0] = an ? __ldcg(xp + g*HH    ) : 0.f;
                pf[g][1] = an ? __ldcg(xp + g*HH + 1) : 0.f;
            }
        }
        asm volatile("barrier.cluster.wait.aligned;" ::: "memory");
    }
}

// ---------------------------------------------------------------------------
// final: logits + mean NLL. Row b's final h lives in buffer (lengths[b] & 1).
// ---------------------------------------------------------------------------
__global__ void final_kernel(
    const float* __restrict__ Wd,
    const float* __restrict__ bd,
    const int*   __restrict__ labels,
    const int*   __restrict__ lengths,
    float*       __restrict__ out,
    int out_size)
{
    __shared__ float red[128];
    __shared__ float wd_s[900];
    int b = threadIdx.x;
    for (int i = b; i < 900; i += 128) wd_s[i] = Wd[i];
    __syncthreads();

    const float* h = g_h[lengths[b] & 1] + b*HH;

    float a0 = bd[0], a1 = bd[1], a2 = bd[2];
    #pragma unroll 5
    for (int k = 0; k < HH; k += 4) {
        float4 hv = *(const float4*)(h + k);
        a0 += hv.x*wd_s[(k+0)*3+0] + hv.y*wd_s[(k+1)*3+0]
            + hv.z*wd_s[(k+2)*3+0] + hv.w*wd_s[(k+3)*3+0];
        a1 += hv.x*wd_s[(k+0)*3+1] + hv.y*wd_s[(k+1)*3+1]
            + hv.z*wd_s[(k+2)*3+1] + hv.w*wd_s[(k+3)*3+1];
        a2 += hv.x*wd_s[(k+0)*3+2] + hv.y*wd_s[(k+1)*3+2]
            + hv.z*wd_s[(k+2)*3+2] + hv.w*wd_s[(k+3)*3+2];
    }
    float mx  = fmaxf(a0, fmaxf(a1, a2));
    float lse = mx + logf(expf(a0 - mx) + expf(a1 - mx) + expf(a2 - mx));
    int   lab = labels[b];
    float sel = (lab == 0) ? a0 : ((lab == 1) ? a1 : a2);
    float nll = lse - sel;

    int off = (out_size >= 385) ? 1 : 0;
    if (out_size >= 384) {
        out[off + b*3 + 0] = a0;
        out[off + b*3 + 1] = a1;
        out[off + b*3 + 2] = a2;
    }
    red[b] = nll;
    __syncthreads();
    for (int s = 64; s; s >>= 1) {
        if (b < s) red[b] += red[b + s];
        __syncthreads();
    }
    if (b == 0 && (off == 1 || out_size < 384)) out[0] = red[0] * (1.f / 128.f);
}

// ---------------------------------------------------------------------------
extern "C" void kernel_launch(void* const* d_in, const int* in_sizes, int n_in,
                              void* d_out, int out_size)
{
    const int*   ids     = (const int*)  d_in[0];
    const int*   lengths = (const int*)  d_in[1];
    const int*   labels  = (const int*)  d_in[2];
    const float* emb     = (const float*)d_in[3];
    const float* W       = (const float*)d_in[4];
    const float* bl      = (const float*)d_in[5];
    const float* Wd      = (const float*)d_in[6];
    const float* bd      = (const float*)d_in[7];
    float* out = (float*)d_out;

    init_kernel<<<(BB*HH + 255)/256, 256>>>(lengths);
    precompute_kernel<<<dim3(19, 4, BB), 256>>>(ids, lengths, emb, W, bl);

    // recurrence: prefer 16-CTA non-portable clusters; fall back to the
    // proven 8-CTA geometry if the device rejects size 16.
    auto k16 = lstm_persistent<20, 40, 44, 3, 16>;
    auto k8  = lstm_persistent<38, 38, 42, 5, 8>;
    cudaFuncSetAttribute(k16, cudaFuncAttributeNonPortableClusterSizeAllowed, 1);

    int maxC = 0;
    {
        cudaLaunchConfig_t q = {};
        q.gridDim  = dim3(NGRP*16, 1, 1);
        q.blockDim = dim3(256, 1, 1);
        q.dynamicSmemBytes = 0;
        cudaOccupancyMaxPotentialClusterSize(&maxC, k16, &q);
    }

    cudaLaunchConfig_t cfg = {};
    cfg.blockDim = dim3(256, 1, 1);
    cfg.dynamicSmemBytes = 0;
    cudaLaunchAttribute at;
    at.id = cudaLaunchAttributeClusterDimension;
    cfg.attrs = &at;
    cfg.numAttrs = 1;

    if (maxC >= 16) {
        at.val.clusterDim.x = 16; at.val.clusterDim.y = 1; at.val.clusterDim.z = 1;
        cfg.gridDim = dim3(NGRP*16, 1, 1);
        cudaLaunchKernelEx(&cfg, k16, W, lengths);
    } else {
        at.val.clusterDim.x = 8; at.val.clusterDim.y = 1; at.val.clusterDim.z = 1;
        cfg.gridDim = dim3(NGRP*8, 1, 1);
        cudaLaunchKernelEx(&cfg, k8, W, lengths);
    }

    final_kernel<<<1, 128>>>(Wd, bd, labels, lengths, out, out_size);
}